// round 16
// baseline (speedup 1.0000x reference)
#include <cuda_runtime.h>

#define N_SAMP 8000
#define T_DIM  64
#define F_DIM  64
#define NCOL   320   // 40 time steps * 8 features
#define W127   91440 // 127*144*5
#define NBIN   2048

// 10.24 MB scratch for ranks: layout [n][t*8+e]
__device__ float g_rank[(size_t)N_SAMP * NCOL];

__device__ __forceinline__ unsigned desc_key(float v){
    unsigned b = __float_as_uint(v);
    unsigned u = b ^ ((b & 0x80000000u) ? 0xFFFFFFFFu : 0x80000000u); // ascending order key
    return ~u;                                                        // descending order key
}
// value-based bin, monotone non-decreasing along descending order.
// width 1/256 over [-4,4]: ~uniform occupancy for N(0,1), avg ~9/bin.
__device__ __forceinline__ int bin_of_val(float v){
    int t = (int)floorf(v * 256.f) + 1024;
    t = min(max(t, 0), NBIN - 1);
    return (NBIN - 1) - t;
}
// recover original float from descending key (exact bijection)
__device__ __forceinline__ float val_of_key(unsigned kk){
    unsigned u = ~kk;
    unsigned b = (u & 0x80000000u) ? (u ^ 0x80000000u) : ~u;
    return __uint_as_float(b);
}

// ---------------------------------------------------------------------------
// Kernel 1: exact descending rank (stable, index tie-break) per (t,e) column.
// One block per column, 512 threads, 16 elems/thread, keys in registers.
// Sorted bins stored as u64 (key<<32 | idx): refinement is a contiguous scan
// of independent LDS.64 with one u64 compare.
// Shared: skey64[8192] (64KB) | hist[2048] (8KB) = 73728 B -> 2 blocks/SM.
// ---------------------------------------------------------------------------
__global__ void __launch_bounds__(512, 2) rank_kernel(const float* __restrict__ x){
    extern __shared__ char sm[];
    unsigned long long* skey = (unsigned long long*)sm;   // 8192 u64
    unsigned*           hist = (unsigned*)(skey + 8192);  // 2048 u32
    __shared__ unsigned wsum[16];

    const int col = blockIdx.x;
    const int tt  = col >> 3;
    const int e   = col & 7;
    const int tid = threadIdx.x;
    const float* xp = x + (size_t)(24 + tt) * F_DIM + e;

    // zero hist, then SYNC before any atomics (round-14 race fix)
    #pragma unroll
    for (int j = 0; j < NBIN/512; j++) hist[tid + j * 512] = 0u;
    __syncthreads();

    unsigned key[16];
    #pragma unroll
    for (int k = 0; k < 16; k++){
        int i = tid + k * 512;
        if (i < N_SAMP){
            float v = __ldg(xp + (size_t)i * (T_DIM * F_DIM));
            key[k] = desc_key(v);
            atomicAdd(&hist[bin_of_val(v)], 1u);
        } else {
            key[k] = 0xFFFFFFFFu;                         // padding sorts last
            atomicAdd(&hist[NBIN - 1], 1u);
        }
    }
    __syncthreads();

    // exclusive scan over 2048 bins: 4 consecutive bins per thread
    unsigned local[4];
    unsigned s = 0;
    const int b0 = tid * 4;
    #pragma unroll
    for (int j = 0; j < 4; j++){ local[j] = hist[b0 + j]; s += local[j]; }
    const unsigned lane = tid & 31, wid = tid >> 5;       // 16 warps
    unsigned inc = s;
    #pragma unroll
    for (int off = 1; off < 32; off <<= 1){
        unsigned o = __shfl_up_sync(0xffffffffu, inc, off);
        if (lane >= off) inc += o;
    }
    if (lane == 31) wsum[wid] = inc;
    __syncthreads();
    if (wid == 0){
        unsigned vv = (lane < 16) ? wsum[lane] : 0u;
        unsigned ii = vv;
        #pragma unroll
        for (int off = 1; off < 32; off <<= 1){
            unsigned o = __shfl_up_sync(0xffffffffu, ii, off);
            if (lane >= off) ii += o;
        }
        if (lane < 16) wsum[lane] = ii - vv;              // exclusive warp prefix
    }
    __syncthreads();
    unsigned run = wsum[wid] + (inc - s);                 // exclusive thread prefix
    #pragma unroll
    for (int j = 0; j < 4; j++){ unsigned c = local[j]; hist[b0 + j] = run; run += c; }
    __syncthreads();

    // scatter (key<<32 | idx); atomic bump turns hist[b] from start into end
    #pragma unroll
    for (int k = 0; k < 16; k++){
        int i = tid + k * 512;
        int b = (i < N_SAMP) ? bin_of_val(val_of_key(key[k])) : (NBIN - 1);
        unsigned p = atomicAdd(&hist[b], 1u);
        skey[p] = ((unsigned long long)key[k] << 32) | (unsigned)i;
    }
    __syncthreads();

    // exact rank: start-of-bin + #(smaller key64 within bin).
    // (km<kk)||(km==kk&&m<i)  <=>  skey64 < mykey64  (indices unique)
    #pragma unroll
    for (int k = 0; k < 16; k++){
        int i = tid + k * 512;
        if (i < N_SAMP){
            int b = bin_of_val(val_of_key(key[k]));
            unsigned start = b ? hist[b - 1] : 0u;        // end of b-1 == start of b
            unsigned end   = hist[b];
            unsigned long long my = ((unsigned long long)key[k] << 32) | (unsigned)i;
            int cnt = 0;
            for (unsigned q = start; q < end; q++)
                cnt += (skey[q] < my);
            g_rank[(size_t)i * NCOL + col] = (float)((int)start + cnt) * (1.0f / 8000.0f);
        }
    }
}

// ---------------------------------------------------------------------------
// Kernel 2: fused window-stats + single-channel conv + leaky-relu + linear.
// 320 threads / 8 samples per block: thread = (sample s, time t).
// ---------------------------------------------------------------------------
__device__ __forceinline__ void ffma2(unsigned long long &d, unsigned long long a, unsigned long long b){
    asm("fma.rn.f32x2 %0, %1, %2, %0;" : "+l"(d) : "l"(a), "l"(b));
}
__device__ __forceinline__ float2 upk2(unsigned long long v){
    float2 f; asm("mov.b64 {%0, %1}, %2;" : "=f"(f.x), "=f"(f.y) : "l"(v)); return f;
}

__global__ void __launch_bounds__(320, 2) main_kernel(
    const float* __restrict__ x, const float* __restrict__ conv_w,
    const float* __restrict__ conv_b, const float* __restrict__ lin_w,
    const float* __restrict__ lin_b, float* __restrict__ out)
{
    extern __shared__ char sm[];
    float* xrowAll = (float*)sm;              // 8 * 40 * 68 = 21760 floats
    float* xeAll   = xrowAll + 8 * 40 * 68;   // 8 * 64 * 8  = 4096
    float* dAll    = xeAll   + 8 * 64 * 8;    // 8 * 200     = 1600
    float* wTs     = dAll    + 8 * 200;       // 720  (wTs[k*144 + c])
    float* linWs   = wTs + 720;               // 36
    float* miscS   = linWs + 36;              // 2

    const int tid   = threadIdx.x;
    const int nbase = blockIdx.x * 8;

    // transpose the single live conv filter: wTs[k][c] = conv_w[127][c][k]
    for (int idx = tid; idx < 720; idx += 320){
        int k = idx / 144, c = idx - k * 144;
        wTs[idx] = conv_w[W127 + c * 5 + k];
    }
    if (tid < 36) linWs[tid] = lin_w[tid];
    if (tid == 36) miscS[0] = conv_b[127];
    if (tid == 37) miscS[1] = lin_b[0];

    // stage rows 24..63, all 64 channels, 8 samples (coalesced, padded stride 68)
    #pragma unroll
    for (int s8 = 0; s8 < 8; s8++){
        const float* src = x + (size_t)(nbase + s8) * (T_DIM * F_DIM) + 1536;
        float* dst = xrowAll + s8 * 2720;
        #pragma unroll
        for (int it = 0; it < 2; it++){
            int f4  = it * 320 + tid;
            int row = f4 >> 4, cc = (f4 & 15) * 4;
            *(float4*)(dst + row * 68 + cc) = *(const float4*)(src + f4 * 4);
        }
    }
    // stage rows 0..63, first 8 features, 8 samples (for window stats)
    #pragma unroll
    for (int it = 0; it < 4; it++){
        int idx = it * 320 + tid;
        if (idx < 1024){
            int s = idx >> 7, q = idx & 127;
            int row = q >> 1, half = (q & 1) * 4;
            *(float4*)(xeAll + s * 512 + row * 8 + half) =
                *(const float4*)(x + (size_t)(nbase + s) * (T_DIM * F_DIM) + row * 64 + half);
        }
    }
    __syncthreads();

    const int s = tid / 40;                   // 0..7 (sample within block)
    const int t = tid - s * 40;               // 0..39
    const int n = nbase + s;
    const float4* xe4 = (const float4*)(xeAll + s * 512);
    float* dW = dAll + s * 200;

    // two independent accumulator sets to halve the fmaf dependency chain
    float dstA[5] = {0.f, 0.f, 0.f, 0.f, 0.f};
    float dstB[5] = {0.f, 0.f, 0.f, 0.f, 0.f};
    auto acc4 = [&](float* acc, int cb, float v0, float v1, float v2, float v3){
        #pragma unroll
        for (int k = 0; k < 5; k++){
            float4 wv = *(const float4*)(wTs + k * 144 + cb);
            acc[k] = fmaf(v0, wv.x, fmaf(v1, wv.y, fmaf(v2, wv.z, fmaf(v3, wv.w, acc[k]))));
        }
    };

    // ---- window stats: rows 5+t..19+t (partial-15), rows 20+t..24+t (5-window),
    //      20-window = partial + 5-window. Rows loaded exactly once. ----
    {
        float sP[8], qP[8], mxP[8], mnP[8];       // first 15 rows of the 20-window
        float s5[8], q5[8], mx5[8], mn5[8];       // last 5 rows == the 5-window
        #pragma unroll
        for (int e2 = 0; e2 < 8; e2++){ sP[e2]=0.f; qP[e2]=0.f; mxP[e2]=-3.4e38f; mnP[e2]=3.4e38f; }
        #pragma unroll
        for (int j = 0; j < 15; j++){
            float4 a = xe4[(5 + t + j) * 2];
            float4 b = xe4[(5 + t + j) * 2 + 1];
            float v[8] = {a.x, a.y, a.z, a.w, b.x, b.y, b.z, b.w};
            #pragma unroll
            for (int e2 = 0; e2 < 8; e2++){
                float vv = v[e2];
                sP[e2] += vv;
                qP[e2]  = fmaf(vv, vv, qP[e2]);
                mxP[e2] = fmaxf(mxP[e2], vv);
                mnP[e2] = fminf(mnP[e2], vv);
            }
        }
        #pragma unroll
        for (int e2 = 0; e2 < 8; e2++){ s5[e2]=0.f; q5[e2]=0.f; mx5[e2]=-3.4e38f; mn5[e2]=3.4e38f; }
        #pragma unroll
        for (int j = 0; j < 5; j++){
            float4 a = xe4[(20 + t + j) * 2];
            float4 b = xe4[(20 + t + j) * 2 + 1];
            float v[8] = {a.x, a.y, a.z, a.w, b.x, b.y, b.z, b.w};
            #pragma unroll
            for (int e2 = 0; e2 < 8; e2++){
                float vv = v[e2];
                s5[e2] += vv;
                q5[e2]  = fmaf(vv, vv, q5[e2]);
                mx5[e2] = fmaxf(mx5[e2], vv);
                mn5[e2] = fminf(mn5[e2], vv);
            }
        }
        float mean20[8], std20[8], mx20[8], mn20[8], mean5[8], std5[8];
        #pragma unroll
        for (int e2 = 0; e2 < 8; e2++){
            float s20 = sP[e2] + s5[e2];
            float q20 = qP[e2] + q5[e2];
            mean20[e2] = s20 * 0.05f;
            std20[e2]  = sqrtf(fmaxf((q20 - s20*s20*0.05f) * (1.0f/19.0f), 0.f));
            mx20[e2]   = fmaxf(mxP[e2], mx5[e2]);
            mn20[e2]   = fminf(mnP[e2], mn5[e2]);
            mean5[e2]  = s5[e2] * 0.2f;
            std5[e2]   = sqrtf(fmaxf((q5[e2] - s5[e2]*s5[e2]*0.2f) * 0.25f, 0.f));
        }
        acc4(dstA, 104, mean20[0], mean20[1], mean20[2], mean20[3]);
        acc4(dstB, 108, mean20[4], mean20[5], mean20[6], mean20[7]);
        acc4(dstA, 112, std20[0], std20[1], std20[2], std20[3]);
        acc4(dstB, 116, std20[4], std20[5], std20[6], std20[7]);
        acc4(dstA, 128, mx20[0], mx20[1], mx20[2], mx20[3]);
        acc4(dstB, 132, mx20[4], mx20[5], mx20[6], mx20[7]);
        acc4(dstA, 136, mn20[0], mn20[1], mn20[2], mn20[3]);
        acc4(dstB, 140, mn20[4], mn20[5], mn20[6], mn20[7]);
        acc4(dstA,  64, mean5[0], mean5[1], mean5[2], mean5[3]);
        acc4(dstB,  68, mean5[4], mean5[5], mean5[6], mean5[7]);
        acc4(dstA,  72, std5[0], std5[1], std5[2], std5[3]);
        acc4(dstB,  76, std5[4], std5[5], std5[6], std5[7]);
        acc4(dstA,  88, mx5[0], mx5[1], mx5[2], mx5[3]);
        acc4(dstB,  92, mx5[4], mx5[5], mx5[6], mx5[7]);
        acc4(dstA,  96, mn5[0], mn5[1], mn5[2], mn5[3]);
        acc4(dstB, 100, mn5[4], mn5[5], mn5[6], mn5[7]);
    }
    // ---- ranks (identical for week & month channel groups) ----
    {
        const float4* rp = (const float4*)(g_rank + (size_t)n * NCOL + t * 8);
        float4 rka = rp[0], rkb = rp[1];
        acc4(dstA,  80, rka.x, rka.y, rka.z, rka.w);
        acc4(dstB,  84, rkb.x, rkb.y, rkb.z, rkb.w);
        acc4(dstA, 120, rka.x, rka.y, rka.z, rka.w);
        acc4(dstB, 124, rkb.x, rkb.y, rkb.z, rkb.w);
    }
    // ---- raw 64-channel dot via packed f32x2 FMA ----
    {
        unsigned long long dax[5], day[5];
        #pragma unroll
        for (int k = 0; k < 5; k++){ dax[k] = 0ULL; day[k] = 0ULL; }
        const ulonglong2* xr2 = (const ulonglong2*)(xrowAll + s * 2720 + t * 68);
        #pragma unroll
        for (int c4 = 0; c4 < 16; c4++){
            ulonglong2 xv = xr2[c4];
            #pragma unroll
            for (int k = 0; k < 5; k++){
                ulonglong2 wv = *(const ulonglong2*)(wTs + k * 144 + c4 * 4);
                ffma2(dax[k], xv.x, wv.x);
                ffma2(day[k], xv.y, wv.y);
            }
        }
        #pragma unroll
        for (int k = 0; k < 5; k++){
            float2 a1 = upk2(dax[k]), a2 = upk2(day[k]);
            dW[t * 5 + k] = (dstA[k] + dstB[k]) + ((a1.x + a1.y) + (a2.x + a2.y));
        }
    }
    __syncthreads();

    // conv taps across t + bias + leaky relu + linear head: warp per sample.
    // 36 positions on 32 lanes: lane p handles position p; lanes 0..3 also
    // handle positions 32..35.
    const int lane = tid & 31, w = tid >> 5;
    if (w < 8){
        const float* dWw = dAll + w * 200;
        const float convB = miscS[0], linB = miscS[1];
        float h = convB;
        #pragma unroll
        for (int k = 0; k < 5; k++) h += dWw[(lane + k) * 5 + k];
        h = (h >= 0.f) ? h : 0.01f * h;
        float c = h * linWs[lane];
        if (lane < 4){
            float h2 = convB;
            #pragma unroll
            for (int k = 0; k < 5; k++) h2 += dWw[(lane + 32 + k) * 5 + k];
            h2 = (h2 >= 0.f) ? h2 : 0.01f * h2;
            c = fmaf(h2, linWs[lane + 32], c);
        }
        #pragma unroll
        for (int off = 16; off; off >>= 1) c += __shfl_down_sync(0xffffffffu, c, off);
        if (lane == 0) out[nbase + w] = c + linB;
    }
}

// ---------------------------------------------------------------------------
extern "C" void kernel_launch(void* const* d_in, const int* in_sizes, int n_in,
                              void* d_out, int out_size)
{
    const float* x      = (const float*)d_in[0];
    const float* conv_w = (const float*)d_in[1];
    const float* conv_b = (const float*)d_in[2];
    const float* lin_w  = (const float*)d_in[3];
    const float* lin_b  = (const float*)d_in[4];
    float* out = (float*)d_out;

    cudaFuncSetAttribute(rank_kernel, cudaFuncAttributeMaxDynamicSharedMemorySize, 73728);
    cudaFuncSetAttribute(main_kernel, cudaFuncAttributeMaxDynamicSharedMemorySize, 112896);

    rank_kernel<<<NCOL, 512, 73728>>>(x);
    main_kernel<<<N_SAMP / 8, 320, 112896>>>(x, conv_w, conv_b, lin_w, lin_b, out);
}

// round 17
// speedup vs baseline: 1.2070x; 1.2070x over previous
#include <cuda_runtime.h>

#define N_SAMP 8000
#define T_DIM  64
#define F_DIM  64
#define NCOL   320   // 40 time steps * 8 features
#define W127   91440 // 127*144*5
#define NBIN   8192
#define XT_S   8192  // padded row stride of xT

// scratch: xT[col][n] (10.5MB), rT[col][n] u16 (5.1MB), r16[n][col] u16 (5.1MB)
__device__ __align__(16) float          g_xT [(size_t)NCOL * XT_S];
__device__ __align__(16) unsigned short g_rT [(size_t)NCOL * N_SAMP];
__device__ __align__(16) unsigned short g_r16[(size_t)N_SAMP * NCOL];

__device__ __forceinline__ unsigned desc_key(float v){
    unsigned b = __float_as_uint(v);
    unsigned u = b ^ ((b & 0x80000000u) ? 0xFFFFFFFFu : 0x80000000u); // ascending key
    return ~u;                                                        // descending key
}

// ---------------------------------------------------------------------------
// xpose_in: gather x[:, 24:64, :8] -> xT[col][n], both sides coalesced.
// 125 blocks x 512 threads, 64 samples/block. smem tile [320][65] f32.
// ---------------------------------------------------------------------------
__global__ void __launch_bounds__(512) xpose_in(const float* __restrict__ x){
    extern __shared__ float tile[];                    // 320*65 = 83200 B
    const int tid = threadIdx.x;
    const int n0  = blockIdx.x * 64;
    #pragma unroll
    for (int j = 0; j < 10; j++){
        int f4 = tid + j * 512;                        // 5120 = 64s * 40t * 2h
        int s = f4 / 80, rem = f4 - s * 80;
        int t = rem >> 1, h = rem & 1;
        float4 v = *(const float4*)(x + (size_t)(n0 + s) * 4096 + (24 + t) * 64 + h * 4);
        int cb = (t * 8 + h * 4) * 65 + s;
        tile[cb] = v.x; tile[cb + 65] = v.y; tile[cb + 130] = v.z; tile[cb + 195] = v.w;
    }
    __syncthreads();
    #pragma unroll
    for (int it = 0; it < 40; it++){
        int i = tid + it * 512;                        // 20480 = 320 cols * 64 s
        int col = i >> 6, s = i & 63;
        g_xT[(size_t)col * XT_S + n0 + s] = tile[col * 65 + s];
    }
}

// ---------------------------------------------------------------------------
// rank_kernel: exact descending rank (stable, index tie-break) per column.
// One block/column, 512 threads, 16 elems/thread via 4x float4 (coalesced).
// Single atomic pass (position captured), 8192 value-bins (~2.2 elems/bin),
// plain-store scatter of u64 (key<<32|idx), contiguous-scan refinement.
// Shared: skey u64[8192] (64KB) + hist u32[8192] (32KB) = 96KB -> 2 blocks/SM.
// ---------------------------------------------------------------------------
__global__ void __launch_bounds__(512, 2) rank_kernel(){
    extern __shared__ char sm[];
    unsigned long long* skey = (unsigned long long*)sm;   // 8192 u64
    unsigned*           hist = (unsigned*)(skey + 8192);  // 8192 u32
    __shared__ unsigned wsum[16];

    const int col = blockIdx.x;
    const int tid = threadIdx.x;
    const float4* xc4 = (const float4*)(g_xT + (size_t)col * XT_S);

    #pragma unroll
    for (int j = 0; j < 16; j++) hist[tid + j * 512] = 0u;
    __syncthreads();

    // count pass: atomicAdd captures within-bin position. pb = bin<<13 | pos.
    unsigned pb[16];
    #pragma unroll
    for (int k = 0; k < 4; k++){
        int idx4 = tid + k * 512;
        float4 v4 = xc4[idx4];
        float vv[4] = {v4.x, v4.y, v4.z, v4.w};
        bool valid = idx4 < 2000;                      // 4*idx4+3 < 8000
        #pragma unroll
        for (int c = 0; c < 4; c++){
            int b;
            if (valid){
                int t = (int)floorf(vv[c] * 1024.f) + 4096;
                t = min(max(t, 0), NBIN - 1);
                b = (NBIN - 1) - t;                    // monotone along descending v
            } else b = NBIN - 1;                       // padding sorts last
            unsigned p = atomicAdd(&hist[b], 1u);
            pb[k * 4 + c] = ((unsigned)b << 13) | p;
        }
    }
    __syncthreads();

    // exclusive scan over 8192 bins: 16 consecutive bins per thread
    unsigned local[16];
    unsigned ssum = 0;
    const int b0 = tid * 16;
    #pragma unroll
    for (int j = 0; j < 16; j++){ local[j] = hist[b0 + j]; ssum += local[j]; }
    const unsigned lane = tid & 31, wid = tid >> 5;    // 16 warps
    unsigned inc = ssum;
    #pragma unroll
    for (int off = 1; off < 32; off <<= 1){
        unsigned o = __shfl_up_sync(0xffffffffu, inc, off);
        if (lane >= off) inc += o;
    }
    if (lane == 31) wsum[wid] = inc;
    __syncthreads();
    if (wid == 0){
        unsigned vv = (lane < 16) ? wsum[lane] : 0u;
        unsigned ii = vv;
        #pragma unroll
        for (int off = 1; off < 32; off <<= 1){
            unsigned o = __shfl_up_sync(0xffffffffu, ii, off);
            if (lane >= off) ii += o;
        }
        if (lane < 16) wsum[lane] = ii - vv;           // exclusive warp prefix
    }
    __syncthreads();
    unsigned run = wsum[wid] + (inc - ssum);           // exclusive thread prefix
    #pragma unroll
    for (int j = 0; j < 16; j++){ unsigned c = local[j]; hist[b0 + j] = run; run += c; }
    __syncthreads();

    // scatter with plain stores: hist[b] stays = bin start
    #pragma unroll
    for (int k = 0; k < 4; k++){
        int idx4 = tid + k * 512;
        float4 v4 = xc4[idx4];                         // L1 hit
        float vv[4] = {v4.x, v4.y, v4.z, v4.w};
        bool valid = idx4 < 2000;
        #pragma unroll
        for (int c = 0; c < 4; c++){
            unsigned m  = pb[k * 4 + c];
            unsigned b  = m >> 13, p = m & 0x1FFFu;
            unsigned key = valid ? desc_key(vv[c]) : 0xFFFFFFFFu;
            unsigned i   = (unsigned)(4 * idx4 + c);
            skey[hist[b] + p] = ((unsigned long long)key << 32) | i;
        }
    }
    __syncthreads();

    // refinement: rank = bin start + #(smaller key64 within bin).
    // (km<kk)||(km==kk&&m<i)  <=>  skey64 < mykey64  (indices unique)
    #pragma unroll
    for (int k = 0; k < 4; k++){
        int idx4 = tid + k * 512;
        if (idx4 < 2000){
            float4 v4 = xc4[idx4];                     // L1 hit
            float vv[4] = {v4.x, v4.y, v4.z, v4.w};
            unsigned short st[4];
            #pragma unroll
            for (int c = 0; c < 4; c++){
                unsigned b = pb[k * 4 + c] >> 13;
                unsigned start = hist[b];
                unsigned end   = (b < NBIN - 1) ? hist[b + 1] : 8192u;
                unsigned key = desc_key(vv[c]);
                unsigned i   = (unsigned)(4 * idx4 + c);
                unsigned long long my = ((unsigned long long)key << 32) | i;
                int cnt = 0;
                for (unsigned q = start; q < end; q++)
                    cnt += (skey[q] < my);
                st[c] = (unsigned short)(start + (unsigned)cnt);
            }
            *(ushort4*)(g_rT + (size_t)col * N_SAMP + 4 * idx4) =
                make_ushort4(st[0], st[1], st[2], st[3]);
        }
    }
}

// ---------------------------------------------------------------------------
// xpose_out: rT[col][n] u16 -> r16[n][col] u16 (so main reads uint4/sample).
// 125 blocks x 512 threads, 64 samples/block. smem tile [320][72] u16.
// ---------------------------------------------------------------------------
__global__ void __launch_bounds__(512) xpose_out(){
    __shared__ unsigned short tile[320 * 72];          // 46080 B
    const int tid = threadIdx.x;
    const int n0  = blockIdx.x * 64;
    #pragma unroll
    for (int it = 0; it < 40; it++){
        int i = tid + it * 512;
        int col = i >> 6, s = i & 63;
        tile[col * 72 + s] = g_rT[(size_t)col * N_SAMP + n0 + s];
    }
    __syncthreads();
    #pragma unroll
    for (int it = 0; it < 5; it++){
        int idx = tid + it * 512;                      // 2560 = 64 s * 40 groups
        int s = idx / 40, g = idx - s * 40;
        unsigned v0 = (unsigned)tile[(g*8+0)*72 + s] | ((unsigned)tile[(g*8+1)*72 + s] << 16);
        unsigned v1 = (unsigned)tile[(g*8+2)*72 + s] | ((unsigned)tile[(g*8+3)*72 + s] << 16);
        unsigned v2 = (unsigned)tile[(g*8+4)*72 + s] | ((unsigned)tile[(g*8+5)*72 + s] << 16);
        unsigned v3 = (unsigned)tile[(g*8+6)*72 + s] | ((unsigned)tile[(g*8+7)*72 + s] << 16);
        *(uint4*)(g_r16 + (size_t)(n0 + s) * NCOL + g * 8) = make_uint4(v0, v1, v2, v3);
    }
}

// ---------------------------------------------------------------------------
// Kernel 2: fused window-stats + single-channel conv + leaky-relu + linear.
// 320 threads / 8 samples per block (R14 structure: main = 58.5us).
// ---------------------------------------------------------------------------
__device__ __forceinline__ void ffma2(unsigned long long &d, unsigned long long a, unsigned long long b){
    asm("fma.rn.f32x2 %0, %1, %2, %0;" : "+l"(d) : "l"(a), "l"(b));
}
__device__ __forceinline__ float2 upk2(unsigned long long v){
    float2 f; asm("mov.b64 {%0, %1}, %2;" : "=f"(f.x), "=f"(f.y) : "l"(v)); return f;
}

__global__ void __launch_bounds__(320, 2) main_kernel(
    const float* __restrict__ x, const float* __restrict__ conv_w,
    const float* __restrict__ conv_b, const float* __restrict__ lin_w,
    const float* __restrict__ lin_b, float* __restrict__ out)
{
    extern __shared__ char sm[];
    float* xrowAll = (float*)sm;              // 8 * 40 * 68 = 21760 floats
    float* xeAll   = xrowAll + 8 * 40 * 68;   // 8 * 64 * 8  = 4096
    float* dAll    = xeAll   + 8 * 64 * 8;    // 8 * 200     = 1600
    float* wTs     = dAll    + 8 * 200;       // 720  (wTs[k*144 + c])
    float* linWs   = wTs + 720;               // 36
    float* miscS   = linWs + 36;              // 2

    const int tid   = threadIdx.x;
    const int nbase = blockIdx.x * 8;

    // transpose the single live conv filter: wTs[k][c] = conv_w[127][c][k]
    for (int idx = tid; idx < 720; idx += 320){
        int k = idx / 144, c = idx - k * 144;
        wTs[idx] = conv_w[W127 + c * 5 + k];
    }
    if (tid < 36) linWs[tid] = lin_w[tid];
    if (tid == 36) miscS[0] = conv_b[127];
    if (tid == 37) miscS[1] = lin_b[0];

    // stage rows 24..63, all 64 channels, 8 samples (coalesced, padded stride 68)
    #pragma unroll
    for (int s8 = 0; s8 < 8; s8++){
        const float* src = x + (size_t)(nbase + s8) * (T_DIM * F_DIM) + 1536;
        float* dst = xrowAll + s8 * 2720;
        #pragma unroll
        for (int it = 0; it < 2; it++){
            int f4  = it * 320 + tid;
            int row = f4 >> 4, cc = (f4 & 15) * 4;
            *(float4*)(dst + row * 68 + cc) = *(const float4*)(src + f4 * 4);
        }
    }
    // stage rows 0..63, first 8 features, 8 samples (for window stats)
    #pragma unroll
    for (int it = 0; it < 4; it++){
        int idx = it * 320 + tid;
        if (idx < 1024){
            int s = idx >> 7, q = idx & 127;
            int row = q >> 1, half = (q & 1) * 4;
            *(float4*)(xeAll + s * 512 + row * 8 + half) =
                *(const float4*)(x + (size_t)(nbase + s) * (T_DIM * F_DIM) + row * 64 + half);
        }
    }
    __syncthreads();

    const int s = tid / 40;                   // 0..7 (sample within block)
    const int t = tid - s * 40;               // 0..39
    const int n = nbase + s;
    const float4* xe4 = (const float4*)(xeAll + s * 512);
    float* dW = dAll + s * 200;

    float dst[5] = {0.f, 0.f, 0.f, 0.f, 0.f};
    auto acc4 = [&](int cb, float v0, float v1, float v2, float v3){
        #pragma unroll
        for (int k = 0; k < 5; k++){
            float4 wv = *(const float4*)(wTs + k * 144 + cb);
            dst[k] = fmaf(v0, wv.x, fmaf(v1, wv.y, fmaf(v2, wv.z, fmaf(v3, wv.w, dst[k]))));
        }
    };

    // ---- 20-window stats (rows 5+t .. 24+t), consumed immediately ----
    {
        float s20[8], q20[8], mx20[8], mn20[8];
        #pragma unroll
        for (int e2 = 0; e2 < 8; e2++){ s20[e2]=0.f; q20[e2]=0.f; mx20[e2]=-3.4e38f; mn20[e2]=3.4e38f; }
        #pragma unroll
        for (int j = 0; j < 20; j++){
            float4 a = xe4[(5 + t + j) * 2];
            float4 b = xe4[(5 + t + j) * 2 + 1];
            float v[8] = {a.x, a.y, a.z, a.w, b.x, b.y, b.z, b.w};
            #pragma unroll
            for (int e2 = 0; e2 < 8; e2++){
                float vv = v[e2];
                s20[e2] += vv;
                q20[e2]  = fmaf(vv, vv, q20[e2]);
                mx20[e2] = fmaxf(mx20[e2], vv);
                mn20[e2] = fminf(mn20[e2], vv);
            }
        }
        float mean20[8], std20[8];
        #pragma unroll
        for (int e2 = 0; e2 < 8; e2++){
            mean20[e2] = s20[e2] * 0.05f;
            std20[e2]  = sqrtf(fmaxf((q20[e2] - s20[e2]*s20[e2]*0.05f) * (1.0f/19.0f), 0.f));
        }
        acc4(104, mean20[0], mean20[1], mean20[2], mean20[3]);
        acc4(108, mean20[4], mean20[5], mean20[6], mean20[7]);
        acc4(112, std20[0], std20[1], std20[2], std20[3]);
        acc4(116, std20[4], std20[5], std20[6], std20[7]);
        acc4(128, mx20[0], mx20[1], mx20[2], mx20[3]);
        acc4(132, mx20[4], mx20[5], mx20[6], mx20[7]);
        acc4(136, mn20[0], mn20[1], mn20[2], mn20[3]);
        acc4(140, mn20[4], mn20[5], mn20[6], mn20[7]);
    }
    // ---- 5-window stats (rows 20+t .. 24+t), consumed immediately ----
    {
        float s5[8], q5[8], mx5[8], mn5[8];
        #pragma unroll
        for (int e2 = 0; e2 < 8; e2++){ s5[e2]=0.f; q5[e2]=0.f; mx5[e2]=-3.4e38f; mn5[e2]=3.4e38f; }
        #pragma unroll
        for (int j = 0; j < 5; j++){
            float4 a = xe4[(20 + t + j) * 2];
            float4 b = xe4[(20 + t + j) * 2 + 1];
            float v[8] = {a.x, a.y, a.z, a.w, b.x, b.y, b.z, b.w};
            #pragma unroll
            for (int e2 = 0; e2 < 8; e2++){
                float vv = v[e2];
                s5[e2] += vv;
                q5[e2]  = fmaf(vv, vv, q5[e2]);
                mx5[e2] = fmaxf(mx5[e2], vv);
                mn5[e2] = fminf(mn5[e2], vv);
            }
        }
        float mean5[8], std5[8];
        #pragma unroll
        for (int e2 = 0; e2 < 8; e2++){
            mean5[e2] = s5[e2] * 0.2f;
            std5[e2]  = sqrtf(fmaxf((q5[e2] - s5[e2]*s5[e2]*0.2f) * 0.25f, 0.f));
        }
        acc4( 64, mean5[0], mean5[1], mean5[2], mean5[3]);
        acc4( 68, mean5[4], mean5[5], mean5[6], mean5[7]);
        acc4( 72, std5[0], std5[1], std5[2], std5[3]);
        acc4( 76, std5[4], std5[5], std5[6], std5[7]);
        acc4( 88, mx5[0], mx5[1], mx5[2], mx5[3]);
        acc4( 92, mx5[4], mx5[5], mx5[6], mx5[7]);
        acc4( 96, mn5[0], mn5[1], mn5[2], mn5[3]);
        acc4(100, mn5[4], mn5[5], mn5[6], mn5[7]);
    }
    // ---- ranks (u16, identical for week & month channel groups) ----
    {
        uint4 rw = *(const uint4*)(g_r16 + (size_t)n * NCOL + t * 8);
        const float sc = 1.0f / 8000.0f;
        float rk[8] = {
            (float)(rw.x & 0xFFFFu) * sc, (float)(rw.x >> 16) * sc,
            (float)(rw.y & 0xFFFFu) * sc, (float)(rw.y >> 16) * sc,
            (float)(rw.z & 0xFFFFu) * sc, (float)(rw.z >> 16) * sc,
            (float)(rw.w & 0xFFFFu) * sc, (float)(rw.w >> 16) * sc };
        acc4( 80, rk[0], rk[1], rk[2], rk[3]);
        acc4( 84, rk[4], rk[5], rk[6], rk[7]);
        acc4(120, rk[0], rk[1], rk[2], rk[3]);
        acc4(124, rk[4], rk[5], rk[6], rk[7]);
    }
    // ---- raw 64-channel dot via packed f32x2 FMA ----
    {
        unsigned long long dax[5], day[5];
        #pragma unroll
        for (int k = 0; k < 5; k++){ dax[k] = 0ULL; day[k] = 0ULL; }
        const ulonglong2* xr2 = (const ulonglong2*)(xrowAll + s * 2720 + t * 68);
        #pragma unroll
        for (int c4 = 0; c4 < 16; c4++){
            ulonglong2 xv = xr2[c4];
            #pragma unroll
            for (int k = 0; k < 5; k++){
                ulonglong2 wv = *(const ulonglong2*)(wTs + k * 144 + c4 * 4);
                ffma2(dax[k], xv.x, wv.x);
                ffma2(day[k], xv.y, wv.y);
            }
        }
        #pragma unroll
        for (int k = 0; k < 5; k++){
            float2 a1 = upk2(dax[k]), a2 = upk2(day[k]);
            dW[t * 5 + k] = dst[k] + ((a1.x + a1.y) + (a2.x + a2.y));
        }
    }
    __syncthreads();

    // conv taps across t + bias + leaky relu + linear head: warp per sample.
    // 36 positions on 32 lanes: lane p handles position p; lanes 0..3 also
    // handle positions 32..35.
    const int lane = tid & 31, w = tid >> 5;
    if (w < 8){
        const float* dWw = dAll + w * 200;
        const float convB = miscS[0], linB = miscS[1];
        float h = convB;
        #pragma unroll
        for (int k = 0; k < 5; k++) h += dWw[(lane + k) * 5 + k];
        h = (h >= 0.f) ? h : 0.01f * h;
        float c = h * linWs[lane];
        if (lane < 4){
            float h2 = convB;
            #pragma unroll
            for (int k = 0; k < 5; k++) h2 += dWw[(lane + 32 + k) * 5 + k];
            h2 = (h2 >= 0.f) ? h2 : 0.01f * h2;
            c = fmaf(h2, linWs[lane + 32], c);
        }
        #pragma unroll
        for (int off = 16; off; off >>= 1) c += __shfl_down_sync(0xffffffffu, c, off);
        if (lane == 0) out[nbase + w] = c + linB;
    }
}

// ---------------------------------------------------------------------------
extern "C" void kernel_launch(void* const* d_in, const int* in_sizes, int n_in,
                              void* d_out, int out_size)
{
    const float* x      = (const float*)d_in[0];
    const float* conv_w = (const float*)d_in[1];
    const float* conv_b = (const float*)d_in[2];
    const float* lin_w  = (const float*)d_in[3];
    const float* lin_b  = (const float*)d_in[4];
    float* out = (float*)d_out;

    cudaFuncSetAttribute(xpose_in,    cudaFuncAttributeMaxDynamicSharedMemorySize, 83200);
    cudaFuncSetAttribute(rank_kernel, cudaFuncAttributeMaxDynamicSharedMemorySize, 98304);
    cudaFuncSetAttribute(main_kernel, cudaFuncAttributeMaxDynamicSharedMemorySize, 112896);

    xpose_in<<<N_SAMP / 64, 512, 83200>>>(x);
    rank_kernel<<<NCOL, 512, 98304>>>();
    xpose_out<<<N_SAMP / 64, 512>>>();
    main_kernel<<<N_SAMP / 8, 320, 112896>>>(x, conv_w, conv_b, lin_w, lin_b, out);
}